// round 2
// baseline (speedup 1.0000x reference)
#include <cuda_runtime.h>
#include <cstdint>
#include <math.h>

// ---------------------------------------------------------------------------
// SpatialBayesianLayer: BitLinear(2F->F) -> ReLU -> BitLinear(F->F) -> sigmoid
//                       -> posterior = prior*lik / sum_S(prior*lik)
// Exact-int8 tensor-core implementation (mma.sync m16n8k32.s8).
// ---------------------------------------------------------------------------

#define QBF 127.0f
#define EPSF 1e-5f

// ---- device scratch (no runtime allocation allowed) ----
__device__ int8_t g_W1q[128 * 256];
__device__ int8_t g_W2q[128 * 128];
__device__ float  g_wsc[2];        // mean |w| (ref's 1/ws), per layer
__device__ double g_norm[1024];    // per (batch, feature) normalizer accumulators
__device__ float  g_rnorm[1024];   // reciprocal normalizers

// ---- shared memory layout (bytes) ----
// XQ   : 128 x 256 int8, row stride 272  (68 words, 68%32==4 -> conflict-free frags)
// union: [ W1S 128x272 | W2S 128x144 | HQ 128x144 ]  overlaid by evidence fp32 staging
// PRIOR: 128 x 132 floats (stride 528 B), persists to epilogue
#define OFF_XQ     0
#define XQ_STR     272
#define OFF_W1     34816
#define W1_STR     272
#define OFF_W2     69632
#define W2_STR     144
#define OFF_HQ     88064
#define HQ_STR     144
#define OFF_XFE    34816      // evidence fp32 staging (dead before W1/W2/HQ live)
#define OFF_PRIOR  106496
#define PR_STR     528
#define OFF_S1     174080
#define OFF_B1     175104
#define OFF_B2     175616
#define OFF_CS     176128
#define SMEM_BYTES 176640

// ---------------------------------------------------------------------------
// int8 tensor-core mma: D(16x8,s32) += A(16x32,s8,row) * B(32x8,s8,col)
// ---------------------------------------------------------------------------
__device__ __forceinline__ void mma_s8(int* c,
                                       unsigned a0, unsigned a1, unsigned a2, unsigned a3,
                                       unsigned b0, unsigned b1) {
    asm volatile(
        "mma.sync.aligned.m16n8k32.row.col.s32.s8.s8.s32 "
        "{%0,%1,%2,%3}, {%4,%5,%6,%7}, {%8,%9}, {%0,%1,%2,%3};"
        : "+r"(c[0]), "+r"(c[1]), "+r"(c[2]), "+r"(c[3])
        : "r"(a0), "r"(a1), "r"(a2), "r"(a3), "r"(b0), "r"(b1));
}

__device__ __forceinline__ int clamp_q(int q) {
    return q < -128 ? -128 : (q > 127 ? 127 : q);
}

__device__ __forceinline__ unsigned pack_q4(float4 v, float s) {
    int q0 = clamp_q(__float2int_rn(v.x * s));
    int q1 = clamp_q(__float2int_rn(v.y * s));
    int q2 = clamp_q(__float2int_rn(v.z * s));
    int q3 = clamp_q(__float2int_rn(v.w * s));
    return (unsigned)(q0 & 255) | ((unsigned)(q1 & 255) << 8) |
           ((unsigned)(q2 & 255) << 16) | ((unsigned)(q3 & 255) << 24);
}

// ---------------------------------------------------------------------------
// Kernel 1: weight ternarization (absmean scale) + zero normalizers.
// block 0 -> W1 (128x256), block 1 -> W2 (128x128)
// ---------------------------------------------------------------------------
__global__ void prep_kernel(const float* __restrict__ W1,
                            const float* __restrict__ W2) {
    __shared__ double red[1024];
    __shared__ float s_ws;
    const int tid = threadIdx.x;
    const float* W = (blockIdx.x == 0) ? W1 : W2;
    int8_t* Wq     = (blockIdx.x == 0) ? g_W1q : g_W2q;
    const int n    = (blockIdx.x == 0) ? 128 * 256 : 128 * 128;

    if (tid < 512) g_norm[blockIdx.x * 512 + tid] = 0.0;

    double acc = 0.0;
    for (int i = tid; i < n; i += 1024) acc += (double)fabsf(W[i]);
    red[tid] = acc;
    __syncthreads();
    for (int s = 512; s > 0; s >>= 1) {
        if (tid < s) red[tid] += red[tid + s];
        __syncthreads();
    }
    if (tid == 0) {
        float m  = fmaxf((float)(red[0] / (double)n), EPSF);
        s_ws = 1.0f / m;                 // ref: ws = 1/clip(mean)
        g_wsc[blockIdx.x] = m;           // ref's per-element t/ws (t = +-1) -> t*m
    }
    __syncthreads();
    const float ws = s_ws;
    for (int i = tid; i < n; i += 1024) {
        float t = rintf(W[i] * ws);      // round half-to-even like jnp.round
        t = fminf(1.0f, fmaxf(-1.0f, t));
        Wq[i] = (int8_t)t;
    }
}

// ---------------------------------------------------------------------------
// Kernel 2: main fused pass. 128 tokens / block, 8 warps, each warp owns 16 rows.
// ---------------------------------------------------------------------------
__global__ __launch_bounds__(256, 1)
void bitnet_main(const float* __restrict__ evid, const float* __restrict__ prior,
                 const float* __restrict__ b1, const float* __restrict__ b2,
                 float* __restrict__ out) {
    extern __shared__ unsigned char sm[];
    const int tid   = threadIdx.x;
    const int lane  = tid & 31;
    const int w     = tid >> 5;
    const int g     = lane >> 2;   // mma group id (row)
    const int tg    = lane & 3;    // thread-in-group (col/k)
    const int token0 = blockIdx.x * 128;
    const int batch  = token0 >> 15;   // 32768 tokens per batch

    float* s1arr = (float*)(sm + OFF_S1);
    float* b1s   = (float*)(sm + OFF_B1);
    float* b2s   = (float*)(sm + OFF_B2);
    float* csum  = (float*)(sm + OFF_CS);

    if (tid < 128) {
        csum[tid] = 0.0f;
        b1s[tid]  = __ldg(&b1[tid]);
        b2s[tid]  = __ldg(&b2[tid]);
    }

    // ---- Phase 0: coalesced fp32 load to smem + per-token absmax ----
    // For each j, each warp covers exactly one token row (row = w + 8*j):
    // warp-shuffle max, single writer per row -> no atomics, no init, no race.
    {
        const float4* pr4 = (const float4*)(prior + (size_t)token0 * 128);
        const float4* ev4 = (const float4*)(evid  + (size_t)token0 * 128);
#pragma unroll
        for (int j = 0; j < 16; j++) {
            int p = tid + 256 * j;            // float4 index
            float4 a = __ldg(&pr4[p]);
            float4 b = __ldg(&ev4[p]);
            int row = p >> 5, c4 = p & 31;
            *(float4*)(sm + OFF_PRIOR + row * PR_STR + c4 * 16) = a;
            *(float4*)(sm + OFF_XFE   + row * PR_STR + c4 * 16) = b;
            float m = fmaxf(fmaxf(fabsf(a.x), fabsf(a.y)), fmaxf(fabsf(a.z), fabsf(a.w)));
            m = fmaxf(m, fmaxf(fmaxf(fabsf(b.x), fabsf(b.y)), fmaxf(fabsf(b.z), fabsf(b.w))));
            m = fmaxf(m, __shfl_xor_sync(0xffffffffu, m, 1));
            m = fmaxf(m, __shfl_xor_sync(0xffffffffu, m, 2));
            m = fmaxf(m, __shfl_xor_sync(0xffffffffu, m, 4));
            m = fmaxf(m, __shfl_xor_sync(0xffffffffu, m, 8));
            m = fmaxf(m, __shfl_xor_sync(0xffffffffu, m, 16));
            if (lane == 0) s1arr[row] = QBF / fmaxf(m, EPSF);
        }
    }
    __syncthreads();

    // ---- Phase 0b: quantize activations to int8 tile XQ [128 x 256] ----
#pragma unroll
    for (int j = 0; j < 16; j++) {
        int p = tid + 256 * j;
        int row = p >> 5, c4 = p & 31;
        float s = s1arr[row];
        float4 a = *(const float4*)(sm + OFF_PRIOR + row * PR_STR + c4 * 16);
        float4 b = *(const float4*)(sm + OFF_XFE   + row * PR_STR + c4 * 16);
        *(unsigned*)(sm + OFF_XQ + row * XQ_STR + c4 * 4)       = pack_q4(a, s);
        *(unsigned*)(sm + OFF_XQ + row * XQ_STR + 128 + c4 * 4) = pack_q4(b, s);
    }
    __syncthreads();   // evidence staging dead; weight tiles may overwrite

    // ---- Phase 0c: weight tiles into padded smem ----
    {
        const int4* w1 = (const int4*)g_W1q;
        for (int c = tid; c < 2048; c += 256) {
            int o = c >> 4, k16 = c & 15;
            *(int4*)(sm + OFF_W1 + o * W1_STR + k16 * 16) = __ldg(&w1[c]);
        }
        const int4* w2 = (const int4*)g_W2q;
        for (int c = tid; c < 1024; c += 256) {
            int o = c >> 3, k16 = c & 7;
            *(int4*)(sm + OFF_W2 + o * W2_STR + k16 * 16) = __ldg(&w2[c]);
        }
    }
    __syncthreads();

    // ---- GEMM1: [16 x 256] x [256 x 128] per warp, int8 exact ----
    const int mb = w * 16;
    int acc[16][4];
#pragma unroll
    for (int n = 0; n < 16; n++) { acc[n][0] = acc[n][1] = acc[n][2] = acc[n][3] = 0; }

#pragma unroll
    for (int k8 = 0; k8 < 8; k8++) {
        const int kb = k8 * 32;
        unsigned a0 = *(const unsigned*)(sm + OFF_XQ + (mb + g)     * XQ_STR + kb + tg * 4);
        unsigned a1 = *(const unsigned*)(sm + OFF_XQ + (mb + g + 8) * XQ_STR + kb + tg * 4);
        unsigned a2 = *(const unsigned*)(sm + OFF_XQ + (mb + g)     * XQ_STR + kb + 16 + tg * 4);
        unsigned a3 = *(const unsigned*)(sm + OFF_XQ + (mb + g + 8) * XQ_STR + kb + 16 + tg * 4);
#pragma unroll
        for (int n = 0; n < 16; n++) {
            unsigned bb0 = *(const unsigned*)(sm + OFF_W1 + (n * 8 + g) * W1_STR + kb + tg * 4);
            unsigned bb1 = *(const unsigned*)(sm + OFF_W1 + (n * 8 + g) * W1_STR + kb + 16 + tg * 4);
            mma_s8(acc[n], a0, a1, a2, a3, bb0, bb1);
        }
    }

    // ---- Epilogue 1: dequant + bias + ReLU, per-row absmax, requantize ----
    const float wsc1 = g_wsc[0];
    const float dq0 = wsc1 * (1.0f / s1arr[mb + g]) * 1.0f;
    const float dq1 = wsc1 * (1.0f / s1arr[mb + g + 8]);
    float hm0 = 0.0f, hm1 = 0.0f;
#pragma unroll
    for (int n = 0; n < 16; n++) {
        const int col = n * 8 + tg * 2;
        float c0 = fmaxf(0.0f, (float)acc[n][0] * dq0 + b1s[col]);
        float c1 = fmaxf(0.0f, (float)acc[n][1] * dq0 + b1s[col + 1]);
        float c2 = fmaxf(0.0f, (float)acc[n][2] * dq1 + b1s[col]);
        float c3 = fmaxf(0.0f, (float)acc[n][3] * dq1 + b1s[col + 1]);
        hm0 = fmaxf(hm0, fmaxf(c0, c1));
        hm1 = fmaxf(hm1, fmaxf(c2, c3));
        acc[n][0] = __float_as_int(c0);  // reuse accumulators as fp32 h storage
        acc[n][1] = __float_as_int(c1);
        acc[n][2] = __float_as_int(c2);
        acc[n][3] = __float_as_int(c3);
    }
    // row max across the 4 lanes of each quad (same g, tg = 0..3)
    hm0 = fmaxf(hm0, __shfl_xor_sync(0xffffffffu, hm0, 1));
    hm0 = fmaxf(hm0, __shfl_xor_sync(0xffffffffu, hm0, 2));
    hm1 = fmaxf(hm1, __shfl_xor_sync(0xffffffffu, hm1, 1));
    hm1 = fmaxf(hm1, __shfl_xor_sync(0xffffffffu, hm1, 2));
    const float s2_0 = QBF / fmaxf(hm0, EPSF);
    const float s2_1 = QBF / fmaxf(hm1, EPSF);

#pragma unroll
    for (int n = 0; n < 16; n++) {
        int q0 = clamp_q(__float2int_rn(__int_as_float(acc[n][0]) * s2_0));
        int q1 = clamp_q(__float2int_rn(__int_as_float(acc[n][1]) * s2_0));
        int q2 = clamp_q(__float2int_rn(__int_as_float(acc[n][2]) * s2_1));
        int q3 = clamp_q(__float2int_rn(__int_as_float(acc[n][3]) * s2_1));
        unsigned short p0 = (unsigned short)((q0 & 255) | ((q1 & 255) << 8));
        unsigned short p1 = (unsigned short)((q2 & 255) | ((q3 & 255) << 8));
        *(unsigned short*)(sm + OFF_HQ + (mb + g)     * HQ_STR + n * 8 + tg * 2) = p0;
        *(unsigned short*)(sm + OFF_HQ + (mb + g + 8) * HQ_STR + n * 8 + tg * 2) = p1;
    }
    __syncwarp();   // warp reads only its own 16 HQ rows below

    // ---- GEMM2: [16 x 128] x [128 x 128] per warp ----
#pragma unroll
    for (int n = 0; n < 16; n++) { acc[n][0] = acc[n][1] = acc[n][2] = acc[n][3] = 0; }
#pragma unroll
    for (int k4 = 0; k4 < 4; k4++) {
        const int kb = k4 * 32;
        unsigned a0 = *(const unsigned*)(sm + OFF_HQ + (mb + g)     * HQ_STR + kb + tg * 4);
        unsigned a1 = *(const unsigned*)(sm + OFF_HQ + (mb + g + 8) * HQ_STR + kb + tg * 4);
        unsigned a2 = *(const unsigned*)(sm + OFF_HQ + (mb + g)     * HQ_STR + kb + 16 + tg * 4);
        unsigned a3 = *(const unsigned*)(sm + OFF_HQ + (mb + g + 8) * HQ_STR + kb + 16 + tg * 4);
#pragma unroll
        for (int n = 0; n < 16; n++) {
            unsigned bb0 = *(const unsigned*)(sm + OFF_W2 + (n * 8 + g) * W2_STR + kb + tg * 4);
            unsigned bb1 = *(const unsigned*)(sm + OFF_W2 + (n * 8 + g) * W2_STR + kb + 16 + tg * 4);
            mma_s8(acc[n], a0, a1, a2, a3, bb0, bb1);
        }
    }

    // ---- Epilogue 2: sigmoid, posterior_unnorm, store, column sums ----
    const float wsc2 = g_wsc[1];
    const float dq20 = wsc2 / s2_0;
    const float dq21 = wsc2 / s2_1;
    const size_t row0 = (size_t)(token0 + mb + g) * 128;
    const size_t row1 = row0 + (size_t)8 * 128;

#pragma unroll
    for (int n = 0; n < 16; n++) {
        const int col = n * 8 + tg * 2;
        float z0 = (float)acc[n][0] * dq20 + b2s[col];
        float z1 = (float)acc[n][1] * dq20 + b2s[col + 1];
        float z2 = (float)acc[n][2] * dq21 + b2s[col];
        float z3 = (float)acc[n][3] * dq21 + b2s[col + 1];
        float l0 = 1.0f / (1.0f + expf(-z0));
        float l1 = 1.0f / (1.0f + expf(-z1));
        float l2 = 1.0f / (1.0f + expf(-z2));
        float l3 = 1.0f / (1.0f + expf(-z3));
        float2 pr0 = *(const float2*)(sm + OFF_PRIOR + (mb + g)     * PR_STR + col * 4);
        float2 pr1 = *(const float2*)(sm + OFF_PRIOR + (mb + g + 8) * PR_STR + col * 4);
        float u0 = pr0.x * l0, u1 = pr0.y * l1;
        float u2 = pr1.x * l2, u3 = pr1.y * l3;
        *(float2*)(out + row0 + col) = make_float2(u0, u1);
        *(float2*)(out + row1 + col) = make_float2(u2, u3);
        // column partial sums over this warp's 16 rows
        float cs0 = u0 + u2, cs1 = u1 + u3;
        cs0 += __shfl_xor_sync(0xffffffffu, cs0, 4);
        cs0 += __shfl_xor_sync(0xffffffffu, cs0, 8);
        cs0 += __shfl_xor_sync(0xffffffffu, cs0, 16);
        cs1 += __shfl_xor_sync(0xffffffffu, cs1, 4);
        cs1 += __shfl_xor_sync(0xffffffffu, cs1, 8);
        cs1 += __shfl_xor_sync(0xffffffffu, cs1, 16);
        if (g == 0) {
            atomicAdd(&csum[col], cs0);
            atomicAdd(&csum[col + 1], cs1);
        }
    }
    __syncthreads();
    if (tid < 128) atomicAdd(&g_norm[batch * 128 + tid], (double)csum[tid]);
}

// ---------------------------------------------------------------------------
// Kernel 3: reciprocal of clipped normalizers
// ---------------------------------------------------------------------------
__global__ void finalize_norm() {
    int i = threadIdx.x;  // 1024 threads
    g_rnorm[i] = (float)(1.0 / fmax(g_norm[i], 1e-10));
}

// ---------------------------------------------------------------------------
// Kernel 4: in-place normalize (float4 streaming)
// ---------------------------------------------------------------------------
__global__ void normalize_kernel(float4* __restrict__ out4) {
    int i = blockIdx.x * 256 + threadIdx.x;    // 8,388,608 float4s
    int b  = i >> 20;                          // 2^20 float4 per batch
    int f4 = i & 31;                           // 32 float4 per feature row
    float4 r = *(const float4*)&g_rnorm[b * 128 + f4 * 4];
    float4 v = out4[i];
    v.x *= r.x; v.y *= r.y; v.z *= r.z; v.w *= r.w;
    out4[i] = v;
}

// ---------------------------------------------------------------------------
extern "C" void kernel_launch(void* const* d_in, const int* in_sizes, int n_in,
                              void* d_out, int out_size) {
    const float* evid  = (const float*)d_in[0];
    const float* prior = (const float*)d_in[1];
    const float* W1    = (const float*)d_in[2];
    const float* b1    = (const float*)d_in[3];
    const float* W2    = (const float*)d_in[4];
    const float* b2    = (const float*)d_in[5];
    float* out = (float*)d_out;

    cudaFuncSetAttribute(bitnet_main, cudaFuncAttributeMaxDynamicSharedMemorySize,
                         SMEM_BYTES);

    prep_kernel<<<2, 1024>>>(W1, W2);
    bitnet_main<<<2048, 256, SMEM_BYTES>>>(evid, prior, b1, b2, out);
    finalize_norm<<<1, 1024>>>();
    normalize_kernel<<<out_size / 1024, 256>>>((float4*)out);
}

// round 4
// speedup vs baseline: 1.6163x; 1.6163x over previous
#include <cuda_runtime.h>
#include <cstdint>
#include <math.h>

// ---------------------------------------------------------------------------
// SpatialBayesianLayer: BitLinear(2F->F) -> ReLU -> BitLinear(F->F) -> sigmoid
//                       -> posterior = prior*lik / sum_S(prior*lik)
// Exact-int8 tensor-core implementation (mma.sync m16n8k32.s8).
// R2/R3: register-direct quantization (no fp32 smem staging), prior re-read
//     from L2 in epilogue, smem 176KB -> 106KB => 2 CTAs/SM.
// ---------------------------------------------------------------------------

#define QBF 127.0f
#define EPSF 1e-5f

// ---- device scratch (no runtime allocation allowed) ----
__device__ int8_t g_W1q[128 * 256];
__device__ int8_t g_W2q[128 * 128];
__device__ float  g_wsc[2];        // mean |w| per layer (ref's 1/ws)
__device__ double g_norm[1024];    // per (batch, feature) normalizer accumulators
__device__ float  g_rnorm[1024];   // reciprocal normalizers

// ---- shared memory layout (bytes) ----
// XQ : 128 x 256 int8, row stride 272 (68 words, 68%32==4 -> conflict-free frags)
// W1 : 128 x 256 int8, stride 272
// W2 : 128 x 128 int8, stride 144
// HQ : 128 x 128 int8, stride 144
#define OFF_XQ     0
#define XQ_STR     272
#define OFF_W1     34816
#define W1_STR     272
#define OFF_W2     69632
#define W2_STR     144
#define OFF_HQ     88064
#define HQ_STR     144
#define OFF_S1     106496
#define OFF_B1     107008
#define OFF_B2     107520
#define OFF_CS     108032
#define SMEM_BYTES 108544

// ---------------------------------------------------------------------------
// int8 tensor-core mma: D(16x8,s32) += A(16x32,s8,row) * B(32x8,s8,col)
// ---------------------------------------------------------------------------
__device__ __forceinline__ void mma_s8(int* c,
                                       unsigned a0, unsigned a1, unsigned a2, unsigned a3,
                                       unsigned b0, unsigned b1) {
    asm volatile(
        "mma.sync.aligned.m16n8k32.row.col.s32.s8.s8.s32 "
        "{%0,%1,%2,%3}, {%4,%5,%6,%7}, {%8,%9}, {%0,%1,%2,%3};"
        : "+r"(c[0]), "+r"(c[1]), "+r"(c[2]), "+r"(c[3])
        : "r"(a0), "r"(a1), "r"(a2), "r"(a3), "r"(b0), "r"(b1));
}

__device__ __forceinline__ int clamp_q(int q) {
    return q < -128 ? -128 : (q > 127 ? 127 : q);
}

__device__ __forceinline__ unsigned pack_q4(float4 v, float s) {
    int q0 = clamp_q(__float2int_rn(v.x * s));
    int q1 = clamp_q(__float2int_rn(v.y * s));
    int q2 = clamp_q(__float2int_rn(v.z * s));
    int q3 = clamp_q(__float2int_rn(v.w * s));
    return (unsigned)(q0 & 255) | ((unsigned)(q1 & 255) << 8) |
           ((unsigned)(q2 & 255) << 16) | ((unsigned)(q3 & 255) << 24);
}

// ---------------------------------------------------------------------------
// Kernel 1: weight ternarization (absmean scale) + zero normalizers.
// block 0 -> W1 (128x256), block 1 -> W2 (128x128)
// ---------------------------------------------------------------------------
__global__ void prep_kernel(const float* __restrict__ W1,
                            const float* __restrict__ W2) {
    __shared__ double red[1024];
    __shared__ float s_ws;
    const int tid = threadIdx.x;
    const float* W = (blockIdx.x == 0) ? W1 : W2;
    int8_t* Wq     = (blockIdx.x == 0) ? g_W1q : g_W2q;
    const int n    = (blockIdx.x == 0) ? 128 * 256 : 128 * 128;

    if (tid < 512) g_norm[blockIdx.x * 512 + tid] = 0.0;

    double acc = 0.0;
    for (int i = tid; i < n; i += 1024) acc += (double)fabsf(W[i]);
    red[tid] = acc;
    __syncthreads();
    for (int s = 512; s > 0; s >>= 1) {
        if (tid < s) red[tid] += red[tid + s];
        __syncthreads();
    }
    if (tid == 0) {
        float m  = fmaxf((float)(red[0] / (double)n), EPSF);
        s_ws = 1.0f / m;                 // ref: ws = 1/clip(mean)
        g_wsc[blockIdx.x] = m;           // ref's t/ws (t = +-1) -> t*m
    }
    __syncthreads();
    const float ws = s_ws;
    for (int i = tid; i < n; i += 1024) {
        float t = rintf(W[i] * ws);      // round half-to-even like jnp.round
        t = fminf(1.0f, fmaxf(-1.0f, t));
        Wq[i] = (int8_t)t;
    }
}

// ---------------------------------------------------------------------------
// Kernel 2: main fused pass. 128 tokens / block, 8 warps, 2 CTAs/SM.
// ---------------------------------------------------------------------------
__global__ __launch_bounds__(256, 2)
void bitnet_main(const float* __restrict__ evid, const float* __restrict__ prior,
                 const float* __restrict__ b1, const float* __restrict__ b2,
                 float* __restrict__ out) {
    extern __shared__ unsigned char sm[];
    const int tid   = threadIdx.x;
    const int lane  = tid & 31;
    const int w     = tid >> 5;
    const int g     = lane >> 2;   // mma group id (row)
    const int tg    = lane & 3;    // thread-in-group (col/k)
    const int token0 = blockIdx.x * 128;
    const int batch  = token0 >> 15;   // 32768 tokens per batch

    float* s1arr = (float*)(sm + OFF_S1);
    float* b1s   = (float*)(sm + OFF_B1);
    float* b2s   = (float*)(sm + OFF_B2);
    float* csum  = (float*)(sm + OFF_CS);

    if (tid < 128) {
        csum[tid] = 0.0f;
        b1s[tid]  = __ldg(&b1[tid]);
        b2s[tid]  = __ldg(&b2[tid]);
    }

    // ---- weight tiles into padded smem (issued early; L2-hot after wave 1) ----
    {
        const int4* w1 = (const int4*)g_W1q;
#pragma unroll
        for (int c = tid; c < 2048; c += 256) {
            int o = c >> 4, k16 = c & 15;
            *(int4*)(sm + OFF_W1 + o * W1_STR + k16 * 16) = __ldg(&w1[c]);
        }
        const int4* w2 = (const int4*)g_W2q;
#pragma unroll
        for (int c = tid; c < 1024; c += 256) {
            int o = c >> 3, k16 = c & 7;
            *(int4*)(sm + OFF_W2 + o * W2_STR + k16 * 16) = __ldg(&w2[c]);
        }
    }

    // ---- Phase 0: load + absmax + quantize, all in registers ----
    // For each j, warp w covers exactly one token row (row = w + 8*j):
    // full row lives in the warp's registers -> shuffle-max -> pack to int8.
    {
        const float4* pr4 = (const float4*)(prior + (size_t)token0 * 128);
        const float4* ev4 = (const float4*)(evid  + (size_t)token0 * 128);
#pragma unroll
        for (int j = 0; j < 16; j++) {
            int p = tid + 256 * j;            // float4 index
            float4 a = __ldg(&pr4[p]);
            float4 b = __ldg(&ev4[p]);
            int row = p >> 5, c4 = p & 31;
            float m = fmaxf(fmaxf(fabsf(a.x), fabsf(a.y)), fmaxf(fabsf(a.z), fabsf(a.w)));
            m = fmaxf(m, fmaxf(fmaxf(fabsf(b.x), fabsf(b.y)), fmaxf(fabsf(b.z), fabsf(b.w))));
            m = fmaxf(m, __shfl_xor_sync(0xffffffffu, m, 1));
            m = fmaxf(m, __shfl_xor_sync(0xffffffffu, m, 2));
            m = fmaxf(m, __shfl_xor_sync(0xffffffffu, m, 4));
            m = fmaxf(m, __shfl_xor_sync(0xffffffffu, m, 8));
            m = fmaxf(m, __shfl_xor_sync(0xffffffffu, m, 16));
            float s = QBF / fmaxf(m, EPSF);
            if (lane == 0) s1arr[row] = s;
            *(unsigned*)(sm + OFF_XQ + row * XQ_STR + c4 * 4)       = pack_q4(a, s);
            *(unsigned*)(sm + OFF_XQ + row * XQ_STR + 128 + c4 * 4) = pack_q4(b, s);
        }
    }
    __syncthreads();

    // ---- GEMM1: [16 x 256] x [256 x 128] per warp, int8 exact ----
    const int mb = w * 16;
    int acc[16][4];
#pragma unroll
    for (int n = 0; n < 16; n++) { acc[n][0] = acc[n][1] = acc[n][2] = acc[n][3] = 0; }

#pragma unroll
    for (int k8 = 0; k8 < 8; k8++) {
        const int kb = k8 * 32;
        unsigned a0 = *(const unsigned*)(sm + OFF_XQ + (mb + g)     * XQ_STR + kb + tg * 4);
        unsigned a1 = *(const unsigned*)(sm + OFF_XQ + (mb + g + 8) * XQ_STR + kb + tg * 4);
        unsigned a2 = *(const unsigned*)(sm + OFF_XQ + (mb + g)     * XQ_STR + kb + 16 + tg * 4);
        unsigned a3 = *(const unsigned*)(sm + OFF_XQ + (mb + g + 8) * XQ_STR + kb + 16 + tg * 4);
#pragma unroll
        for (int n = 0; n < 16; n++) {
            unsigned bb0 = *(const unsigned*)(sm + OFF_W1 + (n * 8 + g) * W1_STR + kb + tg * 4);
            unsigned bb1 = *(const unsigned*)(sm + OFF_W1 + (n * 8 + g) * W1_STR + kb + 16 + tg * 4);
            mma_s8(acc[n], a0, a1, a2, a3, bb0, bb1);
        }
    }

    // ---- Epilogue 1: dequant + bias + ReLU, per-row absmax, requantize ----
    const float wsc1 = g_wsc[0];
    const float dq0 = wsc1 / s1arr[mb + g];
    const float dq1 = wsc1 / s1arr[mb + g + 8];
    float hm0 = 0.0f, hm1 = 0.0f;
#pragma unroll
    for (int n = 0; n < 16; n++) {
        const int col = n * 8 + tg * 2;
        float c0 = fmaxf(0.0f, (float)acc[n][0] * dq0 + b1s[col]);
        float c1 = fmaxf(0.0f, (float)acc[n][1] * dq0 + b1s[col + 1]);
        float c2 = fmaxf(0.0f, (float)acc[n][2] * dq1 + b1s[col]);
        float c3 = fmaxf(0.0f, (float)acc[n][3] * dq1 + b1s[col + 1]);
        hm0 = fmaxf(hm0, fmaxf(c0, c1));
        hm1 = fmaxf(hm1, fmaxf(c2, c3));
        acc[n][0] = __float_as_int(c0);  // reuse accumulators as fp32 h storage
        acc[n][1] = __float_as_int(c1);
        acc[n][2] = __float_as_int(c2);
        acc[n][3] = __float_as_int(c3);
    }
    // row max across the 4 lanes of each quad (same g, tg = 0..3)
    hm0 = fmaxf(hm0, __shfl_xor_sync(0xffffffffu, hm0, 1));
    hm0 = fmaxf(hm0, __shfl_xor_sync(0xffffffffu, hm0, 2));
    hm1 = fmaxf(hm1, __shfl_xor_sync(0xffffffffu, hm1, 1));
    hm1 = fmaxf(hm1, __shfl_xor_sync(0xffffffffu, hm1, 2));
    const float s2_0 = QBF / fmaxf(hm0, EPSF);
    const float s2_1 = QBF / fmaxf(hm1, EPSF);

#pragma unroll
    for (int n = 0; n < 16; n++) {
        int q0 = clamp_q(__float2int_rn(__int_as_float(acc[n][0]) * s2_0));
        int q1 = clamp_q(__float2int_rn(__int_as_float(acc[n][1]) * s2_0));
        int q2 = clamp_q(__float2int_rn(__int_as_float(acc[n][2]) * s2_1));
        int q3 = clamp_q(__float2int_rn(__int_as_float(acc[n][3]) * s2_1));
        unsigned short p0 = (unsigned short)((q0 & 255) | ((q1 & 255) << 8));
        unsigned short p1 = (unsigned short)((q2 & 255) | ((q3 & 255) << 8));
        *(unsigned short*)(sm + OFF_HQ + (mb + g)     * HQ_STR + n * 8 + tg * 2) = p0;
        *(unsigned short*)(sm + OFF_HQ + (mb + g + 8) * HQ_STR + n * 8 + tg * 2) = p1;
    }
    __syncwarp();   // warp reads only its own 16 HQ rows below

    // ---- GEMM2: [16 x 128] x [128 x 128] per warp ----
#pragma unroll
    for (int n = 0; n < 16; n++) { acc[n][0] = acc[n][1] = acc[n][2] = acc[n][3] = 0; }
#pragma unroll
    for (int k4 = 0; k4 < 4; k4++) {
        const int kb = k4 * 32;
        unsigned a0 = *(const unsigned*)(sm + OFF_HQ + (mb + g)     * HQ_STR + kb + tg * 4);
        unsigned a1 = *(const unsigned*)(sm + OFF_HQ + (mb + g + 8) * HQ_STR + kb + tg * 4);
        unsigned a2 = *(const unsigned*)(sm + OFF_HQ + (mb + g)     * HQ_STR + kb + 16 + tg * 4);
        unsigned a3 = *(const unsigned*)(sm + OFF_HQ + (mb + g + 8) * HQ_STR + kb + 16 + tg * 4);
#pragma unroll
        for (int n = 0; n < 16; n++) {
            unsigned bb0 = *(const unsigned*)(sm + OFF_W2 + (n * 8 + g) * W2_STR + kb + tg * 4);
            unsigned bb1 = *(const unsigned*)(sm + OFF_W2 + (n * 8 + g) * W2_STR + kb + 16 + tg * 4);
            mma_s8(acc[n], a0, a1, a2, a3, bb0, bb1);
        }
    }

    // ---- Epilogue 2: sigmoid, posterior_unnorm, store, column sums ----
    // prior is re-read from gmem (L2-hot: same block fetched it in phase 0).
    const float wsc2 = g_wsc[1];
    const float dq20 = wsc2 / s2_0;
    const float dq21 = wsc2 / s2_1;
    const size_t row0 = (size_t)(token0 + mb + g) * 128;
    const size_t row1 = row0 + (size_t)8 * 128;
    const float2* prior2 = (const float2*)prior;

#pragma unroll
    for (int n = 0; n < 16; n++) {
        const int col = n * 8 + tg * 2;
        float z0 = (float)acc[n][0] * dq20 + b2s[col];
        float z1 = (float)acc[n][1] * dq20 + b2s[col + 1];
        float z2 = (float)acc[n][2] * dq21 + b2s[col];
        float z3 = (float)acc[n][3] * dq21 + b2s[col + 1];
        float l0 = 1.0f / (1.0f + __expf(-z0));
        float l1 = 1.0f / (1.0f + __expf(-z1));
        float l2 = 1.0f / (1.0f + __expf(-z2));
        float l3 = 1.0f / (1.0f + __expf(-z3));
        float2 pr0 = __ldg(&prior2[(row0 + col) >> 1]);
        float2 pr1 = __ldg(&prior2[(row1 + col) >> 1]);
        float u0 = pr0.x * l0, u1 = pr0.y * l1;
        float u2 = pr1.x * l2, u3 = pr1.y * l3;
        *(float2*)(out + row0 + col) = make_float2(u0, u1);
        *(float2*)(out + row1 + col) = make_float2(u2, u3);
        // column partial sums over this warp's 16 rows
        float cs0 = u0 + u2, cs1 = u1 + u3;
        cs0 += __shfl_xor_sync(0xffffffffu, cs0, 4);
        cs0 += __shfl_xor_sync(0xffffffffu, cs0, 8);
        cs0 += __shfl_xor_sync(0xffffffffu, cs0, 16);
        cs1 += __shfl_xor_sync(0xffffffffu, cs1, 4);
        cs1 += __shfl_xor_sync(0xffffffffu, cs1, 8);
        cs1 += __shfl_xor_sync(0xffffffffu, cs1, 16);
        if (g == 0) {
            atomicAdd(&csum[col], cs0);
            atomicAdd(&csum[col + 1], cs1);
        }
    }
    __syncthreads();
    if (tid < 128) atomicAdd(&g_norm[batch * 128 + tid], (double)csum[tid]);
}

// ---------------------------------------------------------------------------
// Kernel 3: reciprocal of clipped normalizers
// ---------------------------------------------------------------------------
__global__ void finalize_norm() {
    int i = threadIdx.x;  // 1024 threads
    g_rnorm[i] = (float)(1.0 / fmax(g_norm[i], 1e-10));
}

// ---------------------------------------------------------------------------
// Kernel 4: in-place normalize (float4 streaming)
// ---------------------------------------------------------------------------
__global__ void normalize_kernel(float4* __restrict__ out4) {
    int i = blockIdx.x * 256 + threadIdx.x;    // 8,388,608 float4s
    int b  = i >> 20;                          // 2^20 float4 per batch
    int f4 = i & 31;                           // 32 float4 per feature row
    float4 r = *(const float4*)&g_rnorm[b * 128 + f4 * 4];
    float4 v = out4[i];
    v.x *= r.x; v.y *= r.y; v.z *= r.z; v.w *= r.w;
    out4[i] = v;
}

// ---------------------------------------------------------------------------
extern "C" void kernel_launch(void* const* d_in, const int* in_sizes, int n_in,
                              void* d_out, int out_size) {
    const float* evid  = (const float*)d_in[0];
    const float* prior = (const float*)d_in[1];
    const float* W1    = (const float*)d_in[2];
    const float* b1    = (const float*)d_in[3];
    const float* W2    = (const float*)d_in[4];
    const float* b2    = (const float*)d_in[5];
    float* out = (float*)d_out;

    cudaFuncSetAttribute(bitnet_main, cudaFuncAttributeMaxDynamicSharedMemorySize,
                         SMEM_BYTES);

    prep_kernel<<<2, 1024>>>(W1, W2);
    bitnet_main<<<2048, 256, SMEM_BYTES>>>(evid, prior, b1, b2, out);
    finalize_norm<<<1, 1024>>>();
    normalize_kernel<<<out_size / 1024, 256>>>((float4*)out);
}

// round 5
// speedup vs baseline: 1.7059x; 1.0554x over previous
#include <cuda_runtime.h>
#include <cstdint>
#include <math.h>

// ---------------------------------------------------------------------------
// SpatialBayesianLayer: BitLinear(2F->F) -> ReLU -> BitLinear(F->F) -> sigmoid
//                       -> posterior = prior*lik / sum_S(prior*lik)
// Exact-int8 tensor-core implementation (mma.sync m16n8k32.s8).
// R4: split latency-hostile activation quantization into its own streaming
//     kernel (global int8 XQ + scales); main kernel consumes XQ via cp.async.
// ---------------------------------------------------------------------------

#define QBF 127.0f
#define EPSF 1e-5f

#define NTOK   262144          // 8 * 32768 tokens
// ---- device scratch (no runtime allocation allowed) ----
__device__ unsigned char g_XQ[NTOK * 256];   // quantized [prior|evidence] rows
__device__ float  g_s1[NTOK];                // per-token act scale (QB/absmax)
__device__ int8_t g_W1q[128 * 256];
__device__ int8_t g_W2q[128 * 128];
__device__ float  g_wsc[2];        // mean |w| per layer (ref's 1/ws)
__device__ double g_norm[1024];    // per (batch, feature) normalizer accumulators
__device__ float  g_rnorm[1024];   // reciprocal normalizers

// ---- shared memory layout for bitnet_B (bytes) ----
// XQ : 128 x 256 int8, row stride 272 (68 words, 68%32==4 -> conflict-free frags)
//      (HQ [128 x 128] aliases bytes 0..143 of each XQ row after GEMM1; bands
//       are warp-private so __syncwarp suffices)
// W1 : 128 x 256 int8, stride 272
// W2 : 128 x 128 int8, stride 144
#define OFF_XQ     0
#define XQ_STR     272
#define OFF_W1     34816
#define W1_STR     272
#define OFF_W2     69632
#define W2_STR     144
#define OFF_S1     88064
#define OFF_B1     88576
#define OFF_B2     89088
#define OFF_CS     89600
#define SMEM_BYTES 90112

// ---------------------------------------------------------------------------
__device__ __forceinline__ void mma_s8(int* c,
                                       unsigned a0, unsigned a1, unsigned a2, unsigned a3,
                                       unsigned b0, unsigned b1) {
    asm volatile(
        "mma.sync.aligned.m16n8k32.row.col.s32.s8.s8.s32 "
        "{%0,%1,%2,%3}, {%4,%5,%6,%7}, {%8,%9}, {%0,%1,%2,%3};"
        : "+r"(c[0]), "+r"(c[1]), "+r"(c[2]), "+r"(c[3])
        : "r"(a0), "r"(a1), "r"(a2), "r"(a3), "r"(b0), "r"(b1));
}

__device__ __forceinline__ void cp16(uint32_t dst, const void* src) {
    asm volatile("cp.async.cg.shared.global [%0], [%1], 16;" :: "r"(dst), "l"(src));
}

__device__ __forceinline__ uint32_t smem_u32(const void* p) {
    uint32_t a;
    asm("{ .reg .u64 t; cvta.to.shared.u64 t, %1; cvt.u32.u64 %0, t; }"
        : "=r"(a) : "l"(p));
    return a;
}

__device__ __forceinline__ int clamp_q(int q) {
    return q < -128 ? -128 : (q > 127 ? 127 : q);
}

__device__ __forceinline__ unsigned pack_q4(float4 v, float s) {
    int q0 = clamp_q(__float2int_rn(v.x * s));
    int q1 = clamp_q(__float2int_rn(v.y * s));
    int q2 = clamp_q(__float2int_rn(v.z * s));
    int q3 = clamp_q(__float2int_rn(v.w * s));
    return (unsigned)(q0 & 255) | ((unsigned)(q1 & 255) << 8) |
           ((unsigned)(q2 & 255) << 16) | ((unsigned)(q3 & 255) << 24);
}

// ---------------------------------------------------------------------------
// Kernel 1: weight ternarization (absmean scale) + zero normalizers.
// ---------------------------------------------------------------------------
__global__ void prep_kernel(const float* __restrict__ W1,
                            const float* __restrict__ W2) {
    __shared__ double red[1024];
    __shared__ float s_ws;
    const int tid = threadIdx.x;
    const float* W = (blockIdx.x == 0) ? W1 : W2;
    int8_t* Wq     = (blockIdx.x == 0) ? g_W1q : g_W2q;
    const int n    = (blockIdx.x == 0) ? 128 * 256 : 128 * 128;

    if (tid < 512) g_norm[blockIdx.x * 512 + tid] = 0.0;

    double acc = 0.0;
    for (int i = tid; i < n; i += 1024) acc += (double)fabsf(W[i]);
    red[tid] = acc;
    __syncthreads();
    for (int s = 512; s > 0; s >>= 1) {
        if (tid < s) red[tid] += red[tid + s];
        __syncthreads();
    }
    if (tid == 0) {
        float m  = fmaxf((float)(red[0] / (double)n), EPSF);
        s_ws = 1.0f / m;                 // ref: ws = 1/clip(mean)
        g_wsc[blockIdx.x] = m;           // ref's t/ws (t = +-1) -> t*m
    }
    __syncthreads();
    const float ws = s_ws;
    for (int i = tid; i < n; i += 1024) {
        float t = rintf(W[i] * ws);      // round half-to-even like jnp.round
        t = fminf(1.0f, fmaxf(-1.0f, t));
        Wq[i] = (int8_t)t;
    }
}

// ---------------------------------------------------------------------------
// Kernel 2: streaming activation quantization. 1 warp per token row,
// 8 rows per warp, all loads front-batched (MLP=16).
// ---------------------------------------------------------------------------
__global__ __launch_bounds__(256)
void quant_kernel(const float* __restrict__ evid, const float* __restrict__ prior) {
    const int lane = threadIdx.x & 31;
    const int w    = threadIdx.x >> 5;
    const int r0   = blockIdx.x * 64 + w * 8;   // 4096 blocks * 8 warps * 8 rows

    const float4* pr4 = (const float4*)prior;
    const float4* ev4 = (const float4*)evid;
    unsigned* xq = (unsigned*)g_XQ;

    float4 pa[8], ea[8];
#pragma unroll
    for (int r = 0; r < 8; r++) {
        pa[r] = __ldg(&pr4[(size_t)(r0 + r) * 32 + lane]);
        ea[r] = __ldg(&ev4[(size_t)(r0 + r) * 32 + lane]);
    }
#pragma unroll
    for (int r = 0; r < 8; r++) {
        float4 a = pa[r], b = ea[r];
        float m = fmaxf(fmaxf(fabsf(a.x), fabsf(a.y)), fmaxf(fabsf(a.z), fabsf(a.w)));
        m = fmaxf(m, fmaxf(fmaxf(fabsf(b.x), fabsf(b.y)), fmaxf(fabsf(b.z), fabsf(b.w))));
        m = fmaxf(m, __shfl_xor_sync(0xffffffffu, m, 1));
        m = fmaxf(m, __shfl_xor_sync(0xffffffffu, m, 2));
        m = fmaxf(m, __shfl_xor_sync(0xffffffffu, m, 4));
        m = fmaxf(m, __shfl_xor_sync(0xffffffffu, m, 8));
        m = fmaxf(m, __shfl_xor_sync(0xffffffffu, m, 16));
        float s = QBF / fmaxf(m, EPSF);
        size_t base = (size_t)(r0 + r) * 64;
        xq[base + lane]      = pack_q4(a, s);
        xq[base + 32 + lane] = pack_q4(b, s);
        if (lane == 0) g_s1[r0 + r] = s;
    }
}

// ---------------------------------------------------------------------------
// Kernel 3: main GEMM pass. 128 tokens / block, 8 warps, 2 CTAs/SM.
// All global->smem via cp.async; no fp32 preprocessing.
// ---------------------------------------------------------------------------
__global__ __launch_bounds__(256, 2)
void bitnet_B(const float* __restrict__ prior, const float* __restrict__ b1,
              const float* __restrict__ b2, float* __restrict__ out) {
    extern __shared__ unsigned char sm[];
    const uint32_t sb = smem_u32(sm);
    const int tid   = threadIdx.x;
    const int lane  = tid & 31;
    const int w     = tid >> 5;
    const int g     = lane >> 2;   // mma group id (row)
    const int tg    = lane & 3;    // thread-in-group (col/k)
    const int token0 = blockIdx.x * 128;
    const int batch  = token0 >> 15;   // 32768 tokens per batch

    float* s1arr = (float*)(sm + OFF_S1);
    float* b1s   = (float*)(sm + OFF_B1);
    float* b2s   = (float*)(sm + OFF_B2);
    float* csum  = (float*)(sm + OFF_CS);

    // ---- async stage: XQ tile + weight tiles straight into padded smem ----
#pragma unroll
    for (int i = 0; i < 8; i++) {            // XQ: 2048 x 16B
        int c = tid + 256 * i;
        int row = c >> 4, k = c & 15;
        cp16(sb + OFF_XQ + row * XQ_STR + k * 16,
             g_XQ + (size_t)(token0 + row) * 256 + k * 16);
    }
#pragma unroll
    for (int i = 0; i < 8; i++) {            // W1: 2048 x 16B
        int c = tid + 256 * i;
        int o = c >> 4, k = c & 15;
        cp16(sb + OFF_W1 + o * W1_STR + k * 16, g_W1q + c * 16);
    }
#pragma unroll
    for (int i = 0; i < 4; i++) {            // W2: 1024 x 16B
        int c = tid + 256 * i;
        int o = c >> 3, k = c & 7;
        cp16(sb + OFF_W2 + o * W2_STR + k * 16, g_W2q + c * 16);
    }
    asm volatile("cp.async.commit_group;");

    if (tid < 128) {
        csum[tid]  = 0.0f;
        s1arr[tid] = __ldg(&g_s1[token0 + tid]);
        b1s[tid]   = __ldg(&b1[tid]);
        b2s[tid]   = __ldg(&b2[tid]);
    }
    asm volatile("cp.async.wait_group 0;" ::: "memory");
    __syncthreads();

    // ---- GEMM1: [16 x 256] x [256 x 128] per warp, int8 exact ----
    const int mb = w * 16;
    int acc[16][4];
#pragma unroll
    for (int n = 0; n < 16; n++) { acc[n][0] = acc[n][1] = acc[n][2] = acc[n][3] = 0; }

#pragma unroll
    for (int k8 = 0; k8 < 8; k8++) {
        const int kb = k8 * 32;
        unsigned a0 = *(const unsigned*)(sm + OFF_XQ + (mb + g)     * XQ_STR + kb + tg * 4);
        unsigned a1 = *(const unsigned*)(sm + OFF_XQ + (mb + g + 8) * XQ_STR + kb + tg * 4);
        unsigned a2 = *(const unsigned*)(sm + OFF_XQ + (mb + g)     * XQ_STR + kb + 16 + tg * 4);
        unsigned a3 = *(const unsigned*)(sm + OFF_XQ + (mb + g + 8) * XQ_STR + kb + 16 + tg * 4);
#pragma unroll
        for (int n = 0; n < 16; n++) {
            unsigned bb0 = *(const unsigned*)(sm + OFF_W1 + (n * 8 + g) * W1_STR + kb + tg * 4);
            unsigned bb1 = *(const unsigned*)(sm + OFF_W1 + (n * 8 + g) * W1_STR + kb + 16 + tg * 4);
            mma_s8(acc[n], a0, a1, a2, a3, bb0, bb1);
        }
    }

    // ---- Epilogue 1: dequant + bias + ReLU, per-row absmax, requantize ----
    const float wsc1 = g_wsc[0];
    const float dq0 = wsc1 / s1arr[mb + g];
    const float dq1 = wsc1 / s1arr[mb + g + 8];
    float hm0 = 0.0f, hm1 = 0.0f;
#pragma unroll
    for (int n = 0; n < 16; n++) {
        const int col = n * 8 + tg * 2;
        float c0 = fmaxf(0.0f, (float)acc[n][0] * dq0 + b1s[col]);
        float c1 = fmaxf(0.0f, (float)acc[n][1] * dq0 + b1s[col + 1]);
        float c2 = fmaxf(0.0f, (float)acc[n][2] * dq1 + b1s[col]);
        float c3 = fmaxf(0.0f, (float)acc[n][3] * dq1 + b1s[col + 1]);
        hm0 = fmaxf(hm0, fmaxf(c0, c1));
        hm1 = fmaxf(hm1, fmaxf(c2, c3));
        acc[n][0] = __float_as_int(c0);  // reuse accumulators as fp32 h storage
        acc[n][1] = __float_as_int(c1);
        acc[n][2] = __float_as_int(c2);
        acc[n][3] = __float_as_int(c3);
    }
    hm0 = fmaxf(hm0, __shfl_xor_sync(0xffffffffu, hm0, 1));
    hm0 = fmaxf(hm0, __shfl_xor_sync(0xffffffffu, hm0, 2));
    hm1 = fmaxf(hm1, __shfl_xor_sync(0xffffffffu, hm1, 1));
    hm1 = fmaxf(hm1, __shfl_xor_sync(0xffffffffu, hm1, 2));
    const float s2_0 = QBF / fmaxf(hm0, EPSF);
    const float s2_1 = QBF / fmaxf(hm1, EPSF);

    // HQ aliases the (now dead) XQ band of this warp: rows mb..mb+15, stride 272.
    __syncwarp();
#pragma unroll
    for (int n = 0; n < 16; n++) {
        int q0 = clamp_q(__float2int_rn(__int_as_float(acc[n][0]) * s2_0));
        int q1 = clamp_q(__float2int_rn(__int_as_float(acc[n][1]) * s2_0));
        int q2 = clamp_q(__float2int_rn(__int_as_float(acc[n][2]) * s2_1));
        int q3 = clamp_q(__float2int_rn(__int_as_float(acc[n][3]) * s2_1));
        unsigned short p0 = (unsigned short)((q0 & 255) | ((q1 & 255) << 8));
        unsigned short p1 = (unsigned short)((q2 & 255) | ((q3 & 255) << 8));
        *(unsigned short*)(sm + OFF_XQ + (mb + g)     * XQ_STR + n * 8 + tg * 2) = p0;
        *(unsigned short*)(sm + OFF_XQ + (mb + g + 8) * XQ_STR + n * 8 + tg * 2) = p1;
    }
    __syncwarp();

    // ---- GEMM2: [16 x 128] x [128 x 128] per warp ----
#pragma unroll
    for (int n = 0; n < 16; n++) { acc[n][0] = acc[n][1] = acc[n][2] = acc[n][3] = 0; }
#pragma unroll
    for (int k4 = 0; k4 < 4; k4++) {
        const int kb = k4 * 32;
        unsigned a0 = *(const unsigned*)(sm + OFF_XQ + (mb + g)     * XQ_STR + kb + tg * 4);
        unsigned a1 = *(const unsigned*)(sm + OFF_XQ + (mb + g + 8) * XQ_STR + kb + tg * 4);
        unsigned a2 = *(const unsigned*)(sm + OFF_XQ + (mb + g)     * XQ_STR + kb + 16 + tg * 4);
        unsigned a3 = *(const unsigned*)(sm + OFF_XQ + (mb + g + 8) * XQ_STR + kb + 16 + tg * 4);
#pragma unroll
        for (int n = 0; n < 16; n++) {
            unsigned bb0 = *(const unsigned*)(sm + OFF_W2 + (n * 8 + g) * W2_STR + kb + tg * 4);
            unsigned bb1 = *(const unsigned*)(sm + OFF_W2 + (n * 8 + g) * W2_STR + kb + 16 + tg * 4);
            mma_s8(acc[n], a0, a1, a2, a3, bb0, bb1);
        }
    }

    // ---- Epilogue 2: sigmoid, posterior_unnorm, store, column sums ----
    const float wsc2 = g_wsc[1];
    const float dq20 = wsc2 / s2_0;
    const float dq21 = wsc2 / s2_1;
    const size_t row0 = (size_t)(token0 + mb + g) * 128;
    const size_t row1 = row0 + (size_t)8 * 128;
    const float2* prior2 = (const float2*)prior;

#pragma unroll
    for (int n = 0; n < 16; n++) {
        const int col = n * 8 + tg * 2;
        float z0 = (float)acc[n][0] * dq20 + b2s[col];
        float z1 = (float)acc[n][1] * dq20 + b2s[col + 1];
        float z2 = (float)acc[n][2] * dq21 + b2s[col];
        float z3 = (float)acc[n][3] * dq21 + b2s[col + 1];
        float l0 = 1.0f / (1.0f + __expf(-z0));
        float l1 = 1.0f / (1.0f + __expf(-z1));
        float l2 = 1.0f / (1.0f + __expf(-z2));
        float l3 = 1.0f / (1.0f + __expf(-z3));
        float2 pr0 = __ldg(&prior2[(row0 + col) >> 1]);
        float2 pr1 = __ldg(&prior2[(row1 + col) >> 1]);
        float u0 = pr0.x * l0, u1 = pr0.y * l1;
        float u2 = pr1.x * l2, u3 = pr1.y * l3;
        *(float2*)(out + row0 + col) = make_float2(u0, u1);
        *(float2*)(out + row1 + col) = make_float2(u2, u3);
        float cs0 = u0 + u2, cs1 = u1 + u3;
        cs0 += __shfl_xor_sync(0xffffffffu, cs0, 4);
        cs0 += __shfl_xor_sync(0xffffffffu, cs0, 8);
        cs0 += __shfl_xor_sync(0xffffffffu, cs0, 16);
        cs1 += __shfl_xor_sync(0xffffffffu, cs1, 4);
        cs1 += __shfl_xor_sync(0xffffffffu, cs1, 8);
        cs1 += __shfl_xor_sync(0xffffffffu, cs1, 16);
        if (g == 0) {
            atomicAdd(&csum[col], cs0);
            atomicAdd(&csum[col + 1], cs1);
        }
    }
    __syncthreads();
    if (tid < 128) atomicAdd(&g_norm[batch * 128 + tid], (double)csum[tid]);
}

// ---------------------------------------------------------------------------
__global__ void finalize_norm() {
    int i = threadIdx.x;  // 1024 threads
    g_rnorm[i] = (float)(1.0 / fmax(g_norm[i], 1e-10));
}

// ---------------------------------------------------------------------------
__global__ void normalize_kernel(float4* __restrict__ out4) {
    int i = blockIdx.x * 256 + threadIdx.x;    // 8,388,608 float4s
    int b  = i >> 20;                          // 2^20 float4 per batch
    int f4 = i & 31;                           // 32 float4 per feature row
    float4 r = *(const float4*)&g_rnorm[b * 128 + f4 * 4];
    float4 v = out4[i];
    v.x *= r.x; v.y *= r.y; v.z *= r.z; v.w *= r.w;
    out4[i] = v;
}

// ---------------------------------------------------------------------------
extern "C" void kernel_launch(void* const* d_in, const int* in_sizes, int n_in,
                              void* d_out, int out_size) {
    const float* evid  = (const float*)d_in[0];
    const float* prior = (const float*)d_in[1];
    const float* W1    = (const float*)d_in[2];
    const float* b1    = (const float*)d_in[3];
    const float* W2    = (const float*)d_in[4];
    const float* b2    = (const float*)d_in[5];
    float* out = (float*)d_out;

    cudaFuncSetAttribute(bitnet_B, cudaFuncAttributeMaxDynamicSharedMemorySize,
                         SMEM_BYTES);

    quant_kernel<<<4096, 256>>>(evid, prior);
    prep_kernel<<<2, 1024>>>(W1, W2);
    bitnet_B<<<2048, 256, SMEM_BYTES>>>(prior, b1, b2, out);
    finalize_norm<<<1, 1024>>>();
    normalize_kernel<<<out_size / 1024, 256>>>((float4*)out);
}